// round 17
// baseline (speedup 1.0000x reference)
#include <cuda_runtime.h>
#include <cuda_fp16.h>

#define B_    256
#define T_    4096
#define TWO_N 16
#define H_    64
#define P_    144
#define TBL   128
#define TPB   256
#define TPB1  320
#define TPERB 512            // t's per block (2 per thread)
#define NBLK  (B_*T_/TPERB)  // 2048
#define SUPB  40             // supervised-loss blocks

typedef unsigned long long ull;

__device__ __forceinline__ ull pk2(float lo, float hi) {
    ull r; asm("mov.b64 %0,{%1,%2};" : "=l"(r) : "f"(lo), "f"(hi)); return r;
}
__device__ __forceinline__ float2 upk2(ull a) {
    float2 r; asm("mov.b64 {%0,%1},%2;" : "=f"(r.x), "=f"(r.y) : "l"(a)); return r;
}
__device__ __forceinline__ ull fma2(ull a, ull b, ull c) {
    ull d; asm("fma.rn.f32x2 %0,%1,%2,%3;" : "=l"(d) : "l"(a), "l"(b), "l"(c)); return d;
}
#define MINUS1_2 0xBF800000BF800000ull

__device__ __forceinline__ __half2 u2h(unsigned v) { return *(__half2*)&v; }

// fp16 diff table (16 KB). Row r: word 2k = half2(lat,dlat), 2k+1 = deltas.
__device__ __align__(128) unsigned g_table[TBL][32];
__device__ float g_pd[NBLK];
__device__ float g_pp[NBLK];
__device__ float g_sup[SUPB];

// ---------------------------------------------------------------------------
// Kernel 1: tabulate (R12 version). Blocks 0..SUPB-1 fold sup-loss.
// ---------------------------------------------------------------------------
__global__ __launch_bounds__(TPB1) void build_table(
    const float* __restrict__ W1, const float* __restrict__ b1,
    const float* __restrict__ W2, const float* __restrict__ b2,
    const float* __restrict__ pp, const float* __restrict__ pt,
    const float* __restrict__ icp, const float* __restrict__ ict) {

    __shared__ float s_th[5][64];
    __shared__ float s_dh[5][64];
    __shared__ float s_x[5][16], s_y[5][16];
    __shared__ float s_red[8];

    const int tid = threadIdx.x;
    const int el  = tid >> 6;
    const int j   = tid & 63;
    const int e   = blockIdx.x * 4 + el;
    const bool tb = (blockIdx.x < TBL / 4);

    if (tb && e <= TBL) {
        float tv = (float)e / (float)TBL;
        float w1 = __ldg(W1 + j);
        float u  = fmaf(tv, w1, __ldg(b1 + j));
        float th = tanhf(u);
        s_th[el][j] = th;
        s_dh[el][j] = w1 * (1.f - th * th);
    }
    __syncthreads();

    {
        const int k = tid & 15;
        const int h = (tid >> 4) & 3;
        const int wi = (tid >> 5) & 1;
        float lat = 0.f, dlat = 0.f;
        if (tb && e <= TBL) {
#pragma unroll
            for (int q = 0; q < 16; q++) {
                int jj = h * 16 + q;
                float w2 = __ldg(W2 + jj * 16 + k);
                lat  = fmaf(s_th[el][jj], w2, lat);
                dlat = fmaf(s_dh[el][jj], w2, dlat);
            }
        }
        lat  += __shfl_xor_sync(0xffffffffu, lat,  16);
        dlat += __shfl_xor_sync(0xffffffffu, dlat, 16);
        if (wi == 1 && (tid & 31) < 16) { s_x[el][k] = lat; s_y[el][k] = dlat; }
        __syncthreads();
        if (tb && e <= TBL && wi == 0 && (tid & 31) < 16) {
            s_x[el][k] = lat + s_x[el][k] + __ldg(b2 + k);
            s_y[el][k] = dlat + s_y[el][k];
        }
    }
    __syncthreads();

    if (tb && tid < 64) {
        const int rr = tid >> 4, k = tid & 15;
        const int r = blockIdx.x * 4 + rr;
        if (r < TBL) {
            float v0 = s_x[rr][k],     d0 = s_y[rr][k];
            float v1 = s_x[rr + 1][k], d1 = s_y[rr + 1][k];
            __half2 hv = __floats2half2_rn(v0, d0);
            __half2 hd = __floats2half2_rn(v1 - v0, d1 - d0);
            uint2 o;
            o.x = *(unsigned*)&hv;
            o.y = *(unsigned*)&hd;
            ((uint2*)g_table[r])[k] = o;
        }
    }

    if (blockIdx.x < SUPB && tid < 256) {
        const int ebase = blockIdx.x * 1024 + tid * 4;
        float4 a, t4;
        if (ebase < B_ * P_) {
            a  = __ldg((const float4*)(pp + ebase));
            t4 = __ldg((const float4*)(pt + ebase));
        } else {
            int r = ebase - B_ * P_;
            a  = __ldg((const float4*)(icp + r));
            t4 = __ldg((const float4*)(ict + r));
        }
        float dx = a.x - t4.x, dy = a.y - t4.y, dz = a.z - t4.z, dw = a.w - t4.w;
        float s = fmaf(dx, dx, fmaf(dy, dy, fmaf(dz, dz, dw * dw)));
#pragma unroll
        for (int o = 16; o; o >>= 1) s += __shfl_down_sync(0xffffffffu, s, o);
        if ((tid & 31) == 0) s_red[tid >> 5] = s;
        __syncthreads();
        if (tid == 0) {
            float tot = 0.f;
#pragma unroll
            for (int i = 0; i < 8; i++) tot += s_red[i];
            g_sup[blockIdx.x] = tot;
        }
    }
}

// ---------------------------------------------------------------------------
// Kernel 2: main loss. 2 consecutive t's per thread. NO staging: each thread
// gathers its own two 128-B table rows directly from the L1-resident table
// (16 LDG.128 — same count as the old cooperative path, minus ~100 smem/sync
// instructions). Packed f32x2 compute as in R12.
// ---------------------------------------------------------------------------
__global__ __launch_bounds__(TPB) void main_kernel(
    const float* __restrict__ t_in,
    const float* __restrict__ x_target,
    const float* __restrict__ params) {

    __shared__ float s_par[P_];
    __shared__ ull   s_par2[P_];
    __shared__ float s_rd[TPB / 32], s_rp[TPB / 32];

    const int tid  = threadIdx.x;
    const int b    = blockIdx.x >> 3;
    const int half = blockIdx.x & 7;
    const int t0   = half * TPERB;

    if (tid < P_) {
        float v = __ldg(params + (size_t)b * P_ + tid);
        s_par[tid]  = v;
        s_par2[tid] = pk2(v, v);
    }

    // own t pair (coalesced 64-bit load), index/frac in registers
    float2 tv2 = __ldg((const float2*)(t_in + (size_t)b * T_ + t0) + tid);
    float pA = tv2.x * (float)TBL;
    int   iA = max(0, min((int)pA, TBL - 1));
    __half2 f2A = __float2half2_rn(pA - (float)iA);
    float pB = tv2.y * (float)TBL;
    int   iB = max(0, min((int)pB, TBL - 1));
    __half2 f2B = __float2half2_rn(pB - (float)iB);
    __syncthreads();

    // ---- direct gather + lerp + unpack ----
    const uint4* rowA = (const uint4*)g_table[iA];
    const uint4* rowB = (const uint4*)g_table[iB];

    ull lat2[16], e2[8], nj2[8];
#pragma unroll
    for (int c = 0; c < 8; c++) {
        uint4 wa = __ldg(rowA + c);
        uint4 wb = __ldg(rowB + c);
        __half2 ra0 = __hfma2(f2A, u2h(wa.y), u2h(wa.x));
        __half2 ra1 = __hfma2(f2A, u2h(wa.w), u2h(wa.z));
        __half2 rb0 = __hfma2(f2B, u2h(wb.y), u2h(wb.x));
        __half2 rb1 = __hfma2(f2B, u2h(wb.w), u2h(wb.z));
        float2 A0 = __half22float2(ra0), A1 = __half22float2(ra1);
        float2 B0 = __half22float2(rb0), B1 = __half22float2(rb1);
        const int c0 = 2 * c, c1 = 2 * c + 1;
        if (c0 < 8) {   // compile-time split (c = 0..3)
            lat2[c0] = pk2(A0.x, B0.x);
            e2[c0]   = pk2(A0.x + A0.y, B0.x + B0.y);
            lat2[c1] = pk2(A1.x, B1.x);
            e2[c1]   = pk2(A1.x + A1.y, B1.x + B1.y);
        } else {        // c = 4..7: observables x = relu(q - mu), jvp
            float mu0 = s_par[c0], mu1 = s_par[c1];
            float sA0 = A0.x - mu0, sB0 = B0.x - mu0;
            lat2[c0] = pk2(fmaxf(sA0, 0.f), fmaxf(sB0, 0.f));
            nj2[c0 - 8] = pk2(sA0 > 0.f ? -A0.y : 0.f, sB0 > 0.f ? -B0.y : 0.f);
            float sA1 = A1.x - mu1, sB1 = B1.x - mu1;
            lat2[c1] = pk2(fmaxf(sA1, 0.f), fmaxf(sB1, 0.f));
            nj2[c1 - 8] = pk2(sA1 > 0.f ? -A1.y : 0.f, sB1 > 0.f ? -B1.y : 0.f);
        }
    }

    // ---- physics loss, packed ----
    ull accp = 0ull;
#pragma unroll
    for (int k = 0; k < 8; k++) {
        ull pix = fma2(e2[k], MINUS1_2, s_par2[k]);
#pragma unroll
        for (int j = 0; j < 8; j++)
            pix = fma2(s_par2[16 + k * 8 + j], lat2[8 + j], pix);
        accp = fma2(pix, pix, accp);
        ull m2 = fma2(lat2[8 + k], MINUS1_2, s_par2[8 + k]);
        ull ga = 0ull;
#pragma unroll
        for (int j = 0; j < 8; j++)
            ga = fma2(s_par2[80 + k * 8 + j], lat2[j], ga);
        ull dd = fma2(ga, m2, nj2[k]);
        accp = fma2(dd, dd, accp);
    }

    // ---- data loss, packed (u64 stream loads cover both t's) ----
    ull accd = 0ull;
    const ull* xt = (const ull*)(x_target + (size_t)b * TWO_N * T_ + t0 + 2 * tid);
#pragma unroll
    for (int k = 0; k < 16; k++) {
        ull v = __ldg(xt + (size_t)k * (T_ / 2));
        ull d = fma2(v, MINUS1_2, lat2[k]);
        accd = fma2(d, d, accd);
    }

    // ---- block reduction ----
    float2 ap = upk2(accp), ad = upk2(accd);
    float acc_p = ap.x + ap.y;
    float acc_d = ad.x + ad.y;
#pragma unroll
    for (int o = 16; o; o >>= 1) {
        acc_d += __shfl_down_sync(0xffffffffu, acc_d, o);
        acc_p += __shfl_down_sync(0xffffffffu, acc_p, o);
    }
    const int lane = tid & 31, wid = tid >> 5;
    if (lane == 0) { s_rd[wid] = acc_d; s_rp[wid] = acc_p; }
    __syncthreads();
    if (tid == 0) {
        float sd = 0.f, sp = 0.f;
#pragma unroll
        for (int i = 0; i < TPB / 32; i++) { sd += s_rd[i]; sp += s_rp[i]; }
        g_pd[blockIdx.x] = sd;
        g_pp[blockIdx.x] = sp;
    }
}

// ---------------------------------------------------------------------------
// Kernel 3: finalize — deterministic double sums of tiny partial arrays.
// ---------------------------------------------------------------------------
__global__ void finalize(float* __restrict__ out) {
    const int tid = threadIdx.x;
    double sd = 0.0, sp = 0.0;
    for (int i = tid; i < NBLK; i += 256) {
        sd += (double)g_pd[i];
        sp += (double)g_pp[i];
    }
    double ss = (tid < SUPB) ? (double)g_sup[tid] : 0.0;
    __shared__ double r1[256], r2[256], r3[256];
    r1[tid] = sd; r2[tid] = sp; r3[tid] = ss;
    __syncthreads();
    for (int o = 128; o; o >>= 1) {
        if (tid < o) { r1[tid] += r1[tid + o]; r2[tid] += r2[tid + o]; r3[tid] += r3[tid + o]; }
        __syncthreads();
    }
    if (tid == 0) {
        double res = (r1[0] + r2[0]) / 16777216.0 + r3[0] / 40960.0;
        out[0] = (float)res;
    }
}

// ---------------------------------------------------------------------------
extern "C" void kernel_launch(void* const* d_in, const int* in_sizes, int n_in,
                              void* d_out, int out_size) {
    const float* t   = (const float*)d_in[0];
    const float* xt  = (const float*)d_in[1];
    const float* pp  = (const float*)d_in[2];
    const float* pt  = (const float*)d_in[3];
    const float* icp = (const float*)d_in[4];
    const float* ict = (const float*)d_in[5];
    const float* W1  = (const float*)d_in[6];
    const float* b1  = (const float*)d_in[7];
    const float* W2  = (const float*)d_in[8];
    const float* b2  = (const float*)d_in[9];

    build_table<<<SUPB, TPB1>>>(W1, b1, W2, b2, pp, pt, icp, ict);
    main_kernel<<<NBLK, TPB>>>(t, xt, pp);
    finalize<<<1, 256>>>((float*)d_out);
}